// round 4
// baseline (speedup 1.0000x reference)
#include <cuda_runtime.h>
#include <cuda_bf16.h>
#include <math.h>

// Problem constants
#define BGRAPH 2048
#define NNODE  65536
#define NEDGE  131072
#define DN     256
#define DE     128
#define NITER  6

// ---------------------------------------------------------------------------
// Scratch layout (floats)
// ---------------------------------------------------------------------------
#define OFF_QCAT   0                         // [2048*768] h_n|ro_n|h_e|ro_e
#define OFF_CN     (OFF_QCAT + 2048*768)     // [2048*256]
#define OFF_CE     (OFF_CN   + 2048*256)     // [2048*128]
#define OFF_WN     (OFF_CE   + 2048*128)     // [1024*512] permuted folded weights
#define OFF_BN     (OFF_WN   + 1024*512)     // [1024] permuted bias
#define OFF_WE     (OFF_BN   + 1024)         // [512*256]
#define OFF_BE     (OFF_WE   + 512*256)      // [512]
#define OFF_X1     (OFF_BE   + 512)          // [2048*512]
#define OFF_O2     (OFF_X1   + 2048*512)     // [2048*2048]
#define OFF_X3     (OFF_O2   + 2048*2048)    // [2048*512]
#define OFF_X4     (OFF_X3   + 2048*512)     // [2048*512]
#define SCRATCH_TOTAL (OFF_X4 + 2048*512)

__device__ __align__(256) float g_scratch[SCRATCH_TOTAL];
__device__ int g_starts_n[BGRAPH + 1];
__device__ int g_starts_e[BGRAPH + 1];

// ---------------------------------------------------------------------------
// Segment starts via binary search (seg arrays sorted ascending).
// One launch handles both arrays: bx.y==0 -> node, ==1 -> edge.
// ---------------------------------------------------------------------------
__global__ void seg_starts_kernel(const int* __restrict__ seg_n,
                                  const int* __restrict__ seg_e,
                                  int* __restrict__ starts_n,
                                  int* __restrict__ starts_e) {
    int b = blockIdx.x * blockDim.x + threadIdx.x;
    if (b > BGRAPH) return;
    const int* seg = blockIdx.y ? seg_e : seg_n;
    int* starts    = blockIdx.y ? starts_e : starts_n;
    int M          = blockIdx.y ? NEDGE : NNODE;
    if (b == BGRAPH) { starts[b] = M; return; }
    int lo = 0, hi = M;
    while (lo < hi) {
        int mid = (lo + hi) >> 1;
        if (seg[mid] < b) lo = mid + 1; else hi = mid;
    }
    starts[b] = lo;
}

// ---------------------------------------------------------------------------
// Weight prep: fold Whh into Wih[:, :D], combine biases, AND permute rows so
// output column 4*u+g is gate g (i,f,g,o) of unit u:
//   Wperm[4u+g][k] = Wih[g*D+u][k] + (k<D ? Whh[g*D+u][k] : 0)
//   biasP[4u+g]    = bih[g*D+u] + bhh[g*D+u]
// ---------------------------------------------------------------------------
__global__ void prep_w_kernel(const float* __restrict__ Wih, const float* __restrict__ Whh,
                              const float* __restrict__ bih, const float* __restrict__ bhh,
                              float* __restrict__ Wperm, float* __restrict__ biasP,
                              int D4, int D2, int D) {
    int idx = blockIdx.x * blockDim.x + threadIdx.x;
    int total = D4 * D2;
    if (idx < total) {
        int jp = idx / D2, k = idx % D2;   // output (permuted) row, col
        int u = jp >> 2, g = jp & 3;
        int j = g * D + u;                 // original row
        float v = Wih[(size_t)j * D2 + k];
        if (k < D) v += Whh[(size_t)j * D + k];
        Wperm[idx] = v;
    }
    if (idx < D4) {
        int u = idx >> 2, g = idx & 3;
        int j = g * D + u;
        biasP[idx] = bih[j] + bhh[j];
    }
}

// ---------------------------------------------------------------------------
// LSTM cell helper (gates i,f,g,o).
// ---------------------------------------------------------------------------
__device__ __forceinline__ float lstm_cell(float gi, float gf, float gg, float go,
                                           float c_old, float* c_new) {
    float si = 1.f / (1.f + expf(-gi));
    float sf = 1.f / (1.f + expf(-gf));
    float so = 1.f / (1.f + expf(-go));
    float cn = fmaf(sf, c_old, si * tanhf(gg));
    *c_new = cn;
    return so * tanhf(cn);
}

// ---------------------------------------------------------------------------
// Iteration-0 LSTM for BOTH node and edge: gates = permuted bias, c_old = 0.
// idx < 2048*256 -> node unit; else edge unit.
// ---------------------------------------------------------------------------
__global__ void lstm_first_kernel(const float* __restrict__ bn,
                                  const float* __restrict__ be,
                                  float* __restrict__ cn,
                                  float* __restrict__ ce,
                                  float* __restrict__ qcat) {
    int idx = blockIdx.x * blockDim.x + threadIdx.x;
    const int NTOT = BGRAPH * DN;
    const int ETOT = BGRAPH * DE;
    if (idx >= NTOT + ETOT) return;
    const float* biasP;
    float* c;
    int b, d, h_off;
    if (idx < NTOT) {
        biasP = bn; c = cn; b = idx / DN; d = idx % DN; h_off = 0;
        float cv;
        float h = lstm_cell(biasP[4*d], biasP[4*d+1], biasP[4*d+2], biasP[4*d+3], 0.f, &cv);
        c[idx] = cv;
        qcat[(size_t)b * 768 + h_off + d] = h;
    } else {
        int e = idx - NTOT;
        biasP = be; c = ce; b = e / DE; d = e % DE; h_off = 512;
        float cv;
        float h = lstm_cell(biasP[4*d], biasP[4*d+1], biasP[4*d+2], biasP[4*d+3], 0.f, &cv);
        c[e] = cv;
        qcat[(size_t)b * 768 + h_off + d] = h;
    }
}

// ---------------------------------------------------------------------------
// Fused gate-GEMM + LSTM update for BOTH LSTMs in one launch.
// Grid: (24, 32). bx<16 -> node tile (N=1024,K=512), bx>=16 -> edge (N=512,K=256).
// 64x64 tile, 128 threads, BK=16, TM=8, TN=4. Permuted weights make each
// thread's TN=4 accumulator quad = one unit's (i,f,g,o); cell update in regs.
// ---------------------------------------------------------------------------
__global__ __launch_bounds__(128, 8)
void gates_lstm_kernel(const float* __restrict__ qcat_ro,   // base of qcat
                       const float* __restrict__ Wn, const float* __restrict__ bn,
                       float* __restrict__ cn,
                       const float* __restrict__ We, const float* __restrict__ be,
                       float* __restrict__ ce,
                       float* __restrict__ qcat_out) {
    const int BM = 64, BK = 16, TM = 8, TN = 4;
    __shared__ float As[BK][BM];
    __shared__ float Bs[BK][64];

    int tid = threadIdx.x;
    int bx = blockIdx.x;
    bool is_edge = bx >= 16;

    const float* A     = is_edge ? (qcat_ro + 512) : qcat_ro;
    const float* B     = is_edge ? We : Wn;
    const float* biasP = is_edge ? be : bn;
    float* c           = is_edge ? ce : cn;
    int K              = is_edge ? 256 : 512;
    int D              = is_edge ? 128 : 256;
    int h_off          = is_edge ? 512 : 0;
    int bcol           = (is_edge ? (bx - 16) : bx) * 64;
    int brow           = blockIdx.y * BM;
    const int lda = 768;

    int ar = tid >> 2;            // 0..31
    int ak = (tid & 3) * 4;       // 0,4,8,12
    int tr = (tid >> 4) * TM;     // 0..56
    int tc = (tid & 15) * TN;     // 0..60

    float acc[TM][TN];
#pragma unroll
    for (int i = 0; i < TM; i++)
#pragma unroll
        for (int j = 0; j < TN; j++) acc[i][j] = 0.f;

    for (int k0 = 0; k0 < K; k0 += BK) {
        float4 av0 = *(const float4*)(A + (size_t)(brow + ar) * lda + k0 + ak);
        float4 av1 = *(const float4*)(A + (size_t)(brow + ar + 32) * lda + k0 + ak);
        As[ak + 0][ar] = av0.x; As[ak + 1][ar] = av0.y;
        As[ak + 2][ar] = av0.z; As[ak + 3][ar] = av0.w;
        As[ak + 0][ar + 32] = av1.x; As[ak + 1][ar + 32] = av1.y;
        As[ak + 2][ar + 32] = av1.z; As[ak + 3][ar + 32] = av1.w;
        float4 bv0 = *(const float4*)(B + (size_t)(bcol + ar) * K + k0 + ak);
        float4 bv1 = *(const float4*)(B + (size_t)(bcol + ar + 32) * K + k0 + ak);
        Bs[ak + 0][ar] = bv0.x; Bs[ak + 1][ar] = bv0.y;
        Bs[ak + 2][ar] = bv0.z; Bs[ak + 3][ar] = bv0.w;
        Bs[ak + 0][ar + 32] = bv1.x; Bs[ak + 1][ar + 32] = bv1.y;
        Bs[ak + 2][ar + 32] = bv1.z; Bs[ak + 3][ar + 32] = bv1.w;
        __syncthreads();
#pragma unroll
        for (int k = 0; k < BK; k++) {
            float4 a0 = *(const float4*)&As[k][tr];
            float4 a1 = *(const float4*)&As[k][tr + 4];
            float4 b0 = *(const float4*)&Bs[k][tc];
            float a[TM] = {a0.x, a0.y, a0.z, a0.w, a1.x, a1.y, a1.z, a1.w};
            float b[TN] = {b0.x, b0.y, b0.z, b0.w};
#pragma unroll
            for (int i = 0; i < TM; i++)
#pragma unroll
                for (int j = 0; j < TN; j++)
                    acc[i][j] = fmaf(a[i], b[j], acc[i][j]);
        }
        __syncthreads();
    }

    // LSTM epilogue: this thread's column quad = unit u.
    int cc = bcol + tc;
    int u = cc >> 2;
    float b0 = biasP[cc], b1 = biasP[cc + 1], b2 = biasP[cc + 2], b3 = biasP[cc + 3];
#pragma unroll
    for (int i = 0; i < TM; i++) {
        int r = brow + tr + i;
        float c_old = c[(size_t)r * D + u];
        float cv;
        float h = lstm_cell(acc[i][0] + b0, acc[i][1] + b1, acc[i][2] + b2, acc[i][3] + b3,
                            c_old, &cv);
        c[(size_t)r * D + u] = cv;
        qcat_out[(size_t)r * 768 + h_off + u] = h;
    }
}

// ---------------------------------------------------------------------------
// Unified segment-softmax attention + readout for node AND edge in one launch.
// 4096 blocks x 256 threads. Block b < 2048: node (D=256); else edge (D=128).
// Segments contiguous (sorted seg). All 256 threads join all barriers.
// ---------------------------------------------------------------------------
__global__ __launch_bounds__(256)
void attn_kernel(const float* __restrict__ node_feat,
                 const float* __restrict__ edge_feat,
                 const int* __restrict__ starts_n,
                 const int* __restrict__ starts_e,
                 float* __restrict__ qcat) {
    __shared__ float qsh[256];
    __shared__ float sc[1024];
    __shared__ float red[32];

    int blk = blockIdx.x;
    bool is_edge = blk >= BGRAPH;
    int b = is_edge ? (blk - BGRAPH) : blk;
    const float* feat  = is_edge ? edge_feat : node_feat;
    const int* starts  = is_edge ? starts_e : starts_n;
    int D      = is_edge ? 128 : 256;
    int q_off  = is_edge ? 512 : 0;
    int r_off  = is_edge ? 640 : 256;
    int EPL    = D >> 5;                 // 4 or 8

    int tid = threadIdx.x;
    int warp = tid >> 5, lane = tid & 31;

    if (tid < D) qsh[tid] = qcat[(size_t)b * 768 + q_off + tid];
    int s = starts[b], e = starts[b + 1];
    int cnt = e - s;
    if (cnt > 1024) cnt = 1024;
    __syncthreads();

    // Pass 1: scores (one warp per row, 8 warps)
    for (int j = warp; j < cnt; j += 8) {
        const float* frow = feat + (size_t)(s + j) * D;
        float sum = 0.f;
        for (int u = 0; u < EPL; u++)
            sum = fmaf(frow[lane + 32 * u], qsh[lane + 32 * u], sum);
#pragma unroll
        for (int o = 16; o > 0; o >>= 1) sum += __shfl_xor_sync(0xFFFFFFFFu, sum, o);
        if (lane == 0) sc[j] = sum;
    }
    __syncthreads();

    // Block max
    float m = -INFINITY;
    for (int j = tid; j < cnt; j += 256) m = fmaxf(m, sc[j]);
#pragma unroll
    for (int o = 16; o > 0; o >>= 1) m = fmaxf(m, __shfl_xor_sync(0xFFFFFFFFu, m, o));
    if (lane == 0) red[warp] = m;
    __syncthreads();
    if (tid < 32) {
        float v = (tid < 8) ? red[tid] : -INFINITY;
#pragma unroll
        for (int o = 16; o > 0; o >>= 1) v = fmaxf(v, __shfl_xor_sync(0xFFFFFFFFu, v, o));
        if (tid == 0) red[0] = v;
    }
    __syncthreads();
    m = red[0];
    __syncthreads();

    // exp + sum
    float lsum = 0.f;
    for (int j = tid; j < cnt; j += 256) {
        float ev = expf(sc[j] - m);
        sc[j] = ev;
        lsum += ev;
    }
#pragma unroll
    for (int o = 16; o > 0; o >>= 1) lsum += __shfl_xor_sync(0xFFFFFFFFu, lsum, o);
    if (lane == 0) red[warp] = lsum;
    __syncthreads();
    if (tid < 32) {
        float v = (tid < 8) ? red[tid] : 0.f;
#pragma unroll
        for (int o = 16; o > 0; o >>= 1) v += __shfl_xor_sync(0xFFFFFFFFu, v, o);
        if (tid == 0) red[0] = v;
    }
    __syncthreads();
    float den = red[0];
    float inv = (den > 0.f) ? 1.f / den : 0.f;
    for (int j = tid; j < cnt; j += 256) sc[j] *= inv;
    __syncthreads();

    // Pass 2: readout[d] = sum_j feat[j][d] * alpha[j]  (rows hot in L1)
    if (tid < D) {
        float acc = 0.f;
        for (int j = 0; j < cnt; j++)
            acc = fmaf(feat[(size_t)(s + j) * D + tid], sc[j], acc);
        qcat[(size_t)b * 768 + r_off + tid] = acc;
    }
}

// ---------------------------------------------------------------------------
// SGEMM 128x128 tile (for the big 2048x2048x512 GEMM). B [K,N] row-major.
// ---------------------------------------------------------------------------
template<bool RELU>
__global__ __launch_bounds__(256, 2)
void sgemm_kernel(const float* __restrict__ A, int lda,
                  const float* __restrict__ B,
                  const float* __restrict__ bias,
                  float* __restrict__ C, int ldc,
                  int M, int N, int K) {
    const int BM = 128, BN = 128, BK = 8, TM = 8, TN = 8;
    __shared__ float As[BK][BM];
    __shared__ float Bs[BK][BN];

    int tid = threadIdx.x;
    int block_row = blockIdx.y * BM;
    int block_col = blockIdx.x * BN;

    int a_row = tid >> 1;
    int a_k   = (tid & 1) * 4;

    int tr = (tid >> 4) * TM;
    int tc = (tid & 15) * TN;

    float acc[TM][TN];
#pragma unroll
    for (int i = 0; i < TM; i++)
#pragma unroll
        for (int j = 0; j < TN; j++) acc[i][j] = 0.f;

    for (int k0 = 0; k0 < K; k0 += BK) {
        float4 av = *(const float4*)(A + (size_t)(block_row + a_row) * lda + k0 + a_k);
        As[a_k + 0][a_row] = av.x;
        As[a_k + 1][a_row] = av.y;
        As[a_k + 2][a_row] = av.z;
        As[a_k + 3][a_row] = av.w;
        {
            int b_row = tid >> 5, b_col = (tid & 31) * 4;
            float4 bv = *(const float4*)(B + (size_t)(k0 + b_row) * N + block_col + b_col);
            *(float4*)&Bs[b_row][b_col] = bv;
        }
        __syncthreads();
#pragma unroll
        for (int k = 0; k < BK; k++) {
            float4 a0 = *(const float4*)&As[k][tr];
            float4 a1 = *(const float4*)&As[k][tr + 4];
            float4 b0 = *(const float4*)&Bs[k][tc];
            float4 b1 = *(const float4*)&Bs[k][tc + 4];
            float a[TM] = {a0.x, a0.y, a0.z, a0.w, a1.x, a1.y, a1.z, a1.w};
            float b[TN] = {b0.x, b0.y, b0.z, b0.w, b1.x, b1.y, b1.z, b1.w};
#pragma unroll
            for (int i = 0; i < TM; i++)
#pragma unroll
                for (int j = 0; j < TN; j++)
                    acc[i][j] = fmaf(a[i], b[j], acc[i][j]);
        }
        __syncthreads();
    }

#pragma unroll
    for (int i = 0; i < TM; i++) {
        int r = block_row + tr + i;
#pragma unroll
        for (int j4 = 0; j4 < TN; j4 += 4) {
            int cc = block_col + tc + j4;
            float4 v = make_float4(acc[i][j4], acc[i][j4 + 1], acc[i][j4 + 2], acc[i][j4 + 3]);
            if (bias) {
                v.x += bias[cc]; v.y += bias[cc + 1]; v.z += bias[cc + 2]; v.w += bias[cc + 3];
            }
            if (RELU) {
                v.x = fmaxf(v.x, 0.f); v.y = fmaxf(v.y, 0.f);
                v.z = fmaxf(v.z, 0.f); v.w = fmaxf(v.w, 0.f);
            }
            *(float4*)(C + (size_t)r * ldc + cc) = v;
        }
    }
}

// ---------------------------------------------------------------------------
// SGEMM 64x64 tile, 128 threads, BK=16 — skinny GEMMs (N<=1024), B [K,N].
// ---------------------------------------------------------------------------
template<bool RELU>
__global__ __launch_bounds__(128, 8)
void sgemm64_kernel(const float* __restrict__ A, int lda,
                    const float* __restrict__ B,
                    const float* __restrict__ bias,
                    float* __restrict__ C, int ldc,
                    int M, int N, int K) {
    const int BM = 64, BN = 64, BK = 16, TM = 8, TN = 4;
    __shared__ float As[BK][BM];
    __shared__ float Bs[BK][BN];

    int tid = threadIdx.x;
    int brow = blockIdx.y * BM;
    int bcol = blockIdx.x * BN;

    int ar = tid >> 2;
    int ak = (tid & 3) * 4;

    int tr = (tid >> 4) * TM;
    int tc = (tid & 15) * TN;

    float acc[TM][TN];
#pragma unroll
    for (int i = 0; i < TM; i++)
#pragma unroll
        for (int j = 0; j < TN; j++) acc[i][j] = 0.f;

    for (int k0 = 0; k0 < K; k0 += BK) {
        float4 av0 = *(const float4*)(A + (size_t)(brow + ar) * lda + k0 + ak);
        float4 av1 = *(const float4*)(A + (size_t)(brow + ar + 32) * lda + k0 + ak);
        As[ak + 0][ar] = av0.x; As[ak + 1][ar] = av0.y;
        As[ak + 2][ar] = av0.z; As[ak + 3][ar] = av0.w;
        As[ak + 0][ar + 32] = av1.x; As[ak + 1][ar + 32] = av1.y;
        As[ak + 2][ar + 32] = av1.z; As[ak + 3][ar + 32] = av1.w;
        {
            int br0 = tid >> 4;            // 0..7
            int bc0 = (tid & 15) * 4;      // 0..60
            float4 bv0 = *(const float4*)(B + (size_t)(k0 + br0) * N + bcol + bc0);
            float4 bv1 = *(const float4*)(B + (size_t)(k0 + br0 + 8) * N + bcol + bc0);
            *(float4*)&Bs[br0][bc0] = bv0;
            *(float4*)&Bs[br0 + 8][bc0] = bv1;
        }
        __syncthreads();
#pragma unroll
        for (int k = 0; k < BK; k++) {
            float4 a0 = *(const float4*)&As[k][tr];
            float4 a1 = *(const float4*)&As[k][tr + 4];
            float4 b0 = *(const float4*)&Bs[k][tc];
            float a[TM] = {a0.x, a0.y, a0.z, a0.w, a1.x, a1.y, a1.z, a1.w};
            float b[TN] = {b0.x, b0.y, b0.z, b0.w};
#pragma unroll
            for (int i = 0; i < TM; i++)
#pragma unroll
                for (int j = 0; j < TN; j++)
                    acc[i][j] = fmaf(a[i], b[j], acc[i][j]);
        }
        __syncthreads();
    }

#pragma unroll
    for (int i = 0; i < TM; i++) {
        int r = brow + tr + i;
        int cc = bcol + tc;
        float4 v = make_float4(acc[i][0], acc[i][1], acc[i][2], acc[i][3]);
        if (bias) {
            v.x += bias[cc]; v.y += bias[cc + 1]; v.z += bias[cc + 2]; v.w += bias[cc + 3];
        }
        if (RELU) {
            v.x = fmaxf(v.x, 0.f); v.y = fmaxf(v.y, 0.f);
            v.z = fmaxf(v.z, 0.f); v.w = fmaxf(v.w, 0.f);
        }
        *(float4*)(C + (size_t)r * ldc + cc) = v;
    }
}

// ---------------------------------------------------------------------------
// Final layer: out[b] = dot(x4[b,:512], Wf3) + bf3. One warp per row.
// ---------------------------------------------------------------------------
__global__ void final_dot_kernel(const float* __restrict__ x,
                                 const float* __restrict__ w,
                                 const float* __restrict__ b3,
                                 float* __restrict__ out) {
    int row = blockIdx.x * (blockDim.x >> 5) + (threadIdx.x >> 5);
    int lane = threadIdx.x & 31;
    if (row >= BGRAPH) return;
    const float* xr = x + (size_t)row * 512;
    float s = 0.f;
#pragma unroll
    for (int k = lane; k < 512; k += 32) s = fmaf(xr[k], w[k], s);
#pragma unroll
    for (int o = 16; o > 0; o >>= 1) s += __shfl_xor_sync(0xFFFFFFFFu, s, o);
    if (lane == 0) out[row] = s + b3[0];
}

// ---------------------------------------------------------------------------
// Launch
// ---------------------------------------------------------------------------
extern "C" void kernel_launch(void* const* d_in, const int* in_sizes, int n_in,
                              void* d_out, int out_size) {
    const float* node_feat = (const float*)d_in[0];
    const float* edge_feat = (const float*)d_in[1];
    const int*   node_seg  = (const int*)  d_in[2];
    const int*   edge_seg  = (const int*)  d_in[3];
    const float* Wih_n = (const float*)d_in[4];
    const float* Whh_n = (const float*)d_in[5];
    const float* bih_n = (const float*)d_in[6];
    const float* bhh_n = (const float*)d_in[7];
    const float* Wih_e = (const float*)d_in[8];
    const float* Whh_e = (const float*)d_in[9];
    const float* bih_e = (const float*)d_in[10];
    const float* bhh_e = (const float*)d_in[11];
    const float* Wd1 = (const float*)d_in[12];
    const float* bd1 = (const float*)d_in[13];
    const float* Wd2 = (const float*)d_in[14];
    const float* bd2 = (const float*)d_in[15];
    const float* Wf1 = (const float*)d_in[16];
    const float* bf1 = (const float*)d_in[17];
    const float* Wf2 = (const float*)d_in[18];
    const float* bf2 = (const float*)d_in[19];
    const float* Wf3 = (const float*)d_in[20];
    const float* bf3 = (const float*)d_in[21];
    float* out = (float*)d_out;

    float* base;
    int *stn, *ste;
    cudaGetSymbolAddress((void**)&base, g_scratch);
    cudaGetSymbolAddress((void**)&stn, g_starts_n);
    cudaGetSymbolAddress((void**)&ste, g_starts_e);

    float* qcat = base + OFF_QCAT;
    float* cn   = base + OFF_CN;
    float* ce   = base + OFF_CE;
    float* Wn   = base + OFF_WN;
    float* bn   = base + OFF_BN;
    float* We   = base + OFF_WE;
    float* be   = base + OFF_BE;
    float* x1   = base + OFF_X1;
    float* o2   = base + OFF_O2;
    float* x3   = base + OFF_X3;
    float* x4   = base + OFF_X4;

    seg_starts_kernel<<<dim3(9, 2), 256>>>(node_seg, edge_seg, stn, ste);
    prep_w_kernel<<<(1024 * 512 + 255) / 256, 256>>>(Wih_n, Whh_n, bih_n, bhh_n, Wn, bn,
                                                     1024, 512, 256);
    prep_w_kernel<<<(512 * 256 + 255) / 256, 256>>>(Wih_e, Whh_e, bih_e, bhh_e, We, be,
                                                    512, 256, 128);

    for (int t = 0; t < NITER; t++) {
        if (t == 0) {
            lstm_first_kernel<<<(2048 * 384 + 255) / 256, 256>>>(bn, be, cn, ce, qcat);
        } else {
            gates_lstm_kernel<<<dim3(24, 32), 128>>>(qcat, Wn, bn, cn, We, be, ce, qcat);
        }
        attn_kernel<<<2 * BGRAPH, 256>>>(node_feat, edge_feat, stn, ste, qcat);
    }

    // Decode + FFN
    sgemm64_kernel<true ><<<dim3(512 / 64, 2048 / 64), 128>>>(
        qcat, 768, Wd1, bd1, x1, 512, 2048, 512, 768);
    sgemm_kernel<false><<<dim3(2048 / 128, 2048 / 128), 256>>>(
        x1, 512, Wd2, bd2, o2, 2048, 2048, 2048, 512);
    sgemm64_kernel<true ><<<dim3(512 / 64, 2048 / 64), 128>>>(
        o2, 2048, Wf1, bf1, x3, 512, 2048, 512, 2048);
    sgemm64_kernel<true ><<<dim3(512 / 64, 2048 / 64), 128>>>(
        x3, 512, Wf2, bf2, x4, 512, 2048, 512, 512);
    final_dot_kernel<<<BGRAPH / 8, 256>>>(x4, Wf3, bf3, out);
}

// round 9
// speedup vs baseline: 1.0250x; 1.0250x over previous
#include <cuda_runtime.h>
#include <cuda_bf16.h>
#include <math.h>
#include <stdint.h>

// Problem constants
#define BGRAPH 2048
#define NNODE  65536
#define NEDGE  131072
#define DN     256
#define DE     128
#define NITER  6

// ---------------------------------------------------------------------------
// Scratch layout (floats). TWO qcat buffers (ping-pong across iterations) to
// avoid the read/write race on h columns inside the fused gate-GEMM kernel.
// ---------------------------------------------------------------------------
#define OFF_QC0    0                         // [2048*768] h_n|ro_n|h_e|ro_e
#define OFF_QC1    (OFF_QC0 + 2048*768)      // [2048*768]
#define OFF_CN     (OFF_QC1 + 2048*768)      // [2048*256]
#define OFF_CE     (OFF_CN  + 2048*256)      // [2048*128]
#define OFF_WN     (OFF_CE  + 2048*128)      // [1024*512] permuted folded weights
#define OFF_BN     (OFF_WN  + 1024*512)      // [1024] permuted bias
#define OFF_WE     (OFF_BN  + 1024)          // [512*256]
#define OFF_BE     (OFF_WE  + 512*256)       // [512]
#define OFF_X1     (OFF_BE  + 512)           // [2048*512]
#define OFF_O2     (OFF_X1  + 2048*512)      // [2048*2048]
#define OFF_X3     (OFF_O2  + 2048*2048)     // [2048*512]
#define OFF_X4     (OFF_X3  + 2048*512)      // [2048*512]
#define SCRATCH_TOTAL (OFF_X4 + 2048*512)

__device__ __align__(256) float g_scratch[SCRATCH_TOTAL];
__device__ int g_starts_n[BGRAPH + 1];
__device__ int g_starts_e[BGRAPH + 1];

// ---------------------------------------------------------------------------
// tf32 helpers
// ---------------------------------------------------------------------------
__device__ __forceinline__ uint32_t tf32_of(float x) {
    uint32_t u;
    asm("cvt.rna.tf32.f32 %0, %1;" : "=r"(u) : "f"(x));
    return u;
}

__device__ __forceinline__ void mma8(float4& d, const float* a, const float* b) {
    asm volatile(
        "mma.sync.aligned.m16n8k8.row.col.f32.tf32.tf32.f32 "
        "{%0,%1,%2,%3}, {%4,%5,%6,%7}, {%8,%9}, {%0,%1,%2,%3};"
        : "+f"(d.x), "+f"(d.y), "+f"(d.z), "+f"(d.w)
        : "r"(__float_as_uint(a[0])), "r"(__float_as_uint(a[1])),
          "r"(__float_as_uint(a[2])), "r"(__float_as_uint(a[3])),
          "r"(__float_as_uint(b[0])), "r"(__float_as_uint(b[1])));
}

// smem geometry: 4 tiles of [32 k][72 m-or-n] floats
#define SM_LD 72
#define SM_TILE (32 * SM_LD)     // 2304 floats

__device__ __forceinline__ void split_store(float* __restrict__ H, float* __restrict__ L,
                                            int k, int m, float x) {
    float hi = __uint_as_float(tf32_of(x));
    H[k * SM_LD + m] = hi;
    L[k * SM_LD + m] = __uint_as_float(tf32_of(x - hi));
}

// ---------------------------------------------------------------------------
// 3xTF32 mainloop: C_tile[64x64] = A[brow:brow+64, :K] * B
//   BT=true : B stored [N,K] row-major (C = A @ W^T)
//   BT=false: B stored [K,N] row-major (C = A @ W)
// 128 threads = 4 warps; warp (w>>1, w&1) owns a 32x32 quadrant.
// On exit all threads have passed a final __syncthreads (smem reusable).
// ---------------------------------------------------------------------------
template<bool BT>
__device__ __forceinline__ void tf32_mainloop(
    const float* __restrict__ A, int lda,
    const float* __restrict__ B, int K, int N,
    int brow, int bcol, float* __restrict__ sm,
    float4 acc[2][4], int tid)
{
    float* Ah = sm;
    float* Al = sm + SM_TILE;
    float* Bh = sm + 2 * SM_TILE;
    float* Bl = sm + 3 * SM_TILE;

    int lane = tid & 31, warp = tid >> 5;
    int wm = (warp >> 1) * 32, wn = (warp & 1) * 32;
    int l4 = lane & 3, lg = lane >> 2;

    for (int k0 = 0; k0 < K; k0 += 32) {
        {
            int ar = tid >> 1;
            int akk = (tid & 1) * 16;
            const float* src = A + (size_t)(brow + ar) * lda + k0 + akk;
#pragma unroll
            for (int i = 0; i < 4; i++) {
                float4 v = *(const float4*)(src + i * 4);
                int kk = akk + i * 4;
                split_store(Ah, Al, kk + 0, ar, v.x);
                split_store(Ah, Al, kk + 1, ar, v.y);
                split_store(Ah, Al, kk + 2, ar, v.z);
                split_store(Ah, Al, kk + 3, ar, v.w);
            }
        }
        if (BT) {
            int br = tid >> 1;
            int bkk = (tid & 1) * 16;
            const float* src = B + (size_t)(bcol + br) * K + k0 + bkk;
#pragma unroll
            for (int i = 0; i < 4; i++) {
                float4 v = *(const float4*)(src + i * 4);
                int kk = bkk + i * 4;
                split_store(Bh, Bl, kk + 0, br, v.x);
                split_store(Bh, Bl, kk + 1, br, v.y);
                split_store(Bh, Bl, kk + 2, br, v.z);
                split_store(Bh, Bl, kk + 3, br, v.w);
            }
        } else {
            int bk = tid >> 2;
            int bn0 = (tid & 3) * 16;
            const float* src = B + (size_t)(k0 + bk) * N + bcol + bn0;
#pragma unroll
            for (int i = 0; i < 4; i++) {
                float4 v = *(const float4*)(src + i * 4);
                int nn = bn0 + i * 4;
                split_store(Bh, Bl, bk, nn + 0, v.x);
                split_store(Bh, Bl, bk, nn + 1, v.y);
                split_store(Bh, Bl, bk, nn + 2, v.z);
                split_store(Bh, Bl, bk, nn + 3, v.w);
            }
        }
        __syncthreads();

#pragma unroll
        for (int ks = 0; ks < 4; ks++) {
            int kb = ks * 8;
            float ah[2][4], al[2][4];
#pragma unroll
            for (int mt = 0; mt < 2; mt++) {
                int m0 = wm + mt * 16 + lg;
                int ka = (kb + l4) * SM_LD;
                int kb4 = (kb + l4 + 4) * SM_LD;
                ah[mt][0] = Ah[ka + m0];
                ah[mt][1] = Ah[ka + m0 + 8];
                ah[mt][2] = Ah[kb4 + m0];
                ah[mt][3] = Ah[kb4 + m0 + 8];
                al[mt][0] = Al[ka + m0];
                al[mt][1] = Al[ka + m0 + 8];
                al[mt][2] = Al[kb4 + m0];
                al[mt][3] = Al[kb4 + m0 + 8];
            }
            float bh[4][2], bl[4][2];
#pragma unroll
            for (int nt = 0; nt < 4; nt++) {
                int n0 = wn + nt * 8 + lg;
                bh[nt][0] = Bh[(kb + l4) * SM_LD + n0];
                bh[nt][1] = Bh[(kb + l4 + 4) * SM_LD + n0];
                bl[nt][0] = Bl[(kb + l4) * SM_LD + n0];
                bl[nt][1] = Bl[(kb + l4 + 4) * SM_LD + n0];
            }
#pragma unroll
            for (int mt = 0; mt < 2; mt++)
#pragma unroll
                for (int nt = 0; nt < 4; nt++) {
                    mma8(acc[mt][nt], ah[mt], bh[nt]);   // hi*hi
                    mma8(acc[mt][nt], ah[mt], bl[nt]);   // hi*lo
                    mma8(acc[mt][nt], al[mt], bh[nt]);   // lo*hi
                }
        }
        __syncthreads();
    }
}

// ---------------------------------------------------------------------------
// Segment starts via binary search (seg arrays sorted ascending).
// ---------------------------------------------------------------------------
__global__ void seg_starts_kernel(const int* __restrict__ seg_n,
                                  const int* __restrict__ seg_e,
                                  int* __restrict__ starts_n,
                                  int* __restrict__ starts_e) {
    int b = blockIdx.x * blockDim.x + threadIdx.x;
    if (b > BGRAPH) return;
    const int* seg = blockIdx.y ? seg_e : seg_n;
    int* starts    = blockIdx.y ? starts_e : starts_n;
    int M          = blockIdx.y ? NEDGE : NNODE;
    if (b == BGRAPH) { starts[b] = M; return; }
    int lo = 0, hi = M;
    while (lo < hi) {
        int mid = (lo + hi) >> 1;
        if (seg[mid] < b) lo = mid + 1; else hi = mid;
    }
    starts[b] = lo;
}

// ---------------------------------------------------------------------------
// Weight prep: fold Whh into Wih[:, :D], combine biases, permute rows so
// output column 4*u+g is gate g (i,f,g,o) of unit u.
// ---------------------------------------------------------------------------
__global__ void prep_w_kernel(const float* __restrict__ Wih, const float* __restrict__ Whh,
                              const float* __restrict__ bih, const float* __restrict__ bhh,
                              float* __restrict__ Wperm, float* __restrict__ biasP,
                              int D4, int D2, int D) {
    int idx = blockIdx.x * blockDim.x + threadIdx.x;
    int total = D4 * D2;
    if (idx < total) {
        int jp = idx / D2, k = idx % D2;
        int u = jp >> 2, g = jp & 3;
        int j = g * D + u;
        float v = Wih[(size_t)j * D2 + k];
        if (k < D) v += Whh[(size_t)j * D + k];
        Wperm[idx] = v;
    }
    if (idx < D4) {
        int u = idx >> 2, g = idx & 3;
        int j = g * D + u;
        biasP[idx] = bih[j] + bhh[j];
    }
}

// ---------------------------------------------------------------------------
// LSTM cell (gates i,f,g,o).
// ---------------------------------------------------------------------------
__device__ __forceinline__ float lstm_cell(float gi, float gf, float gg, float go,
                                           float c_old, float* c_new) {
    float si = 1.f / (1.f + expf(-gi));
    float sf = 1.f / (1.f + expf(-gf));
    float so = 1.f / (1.f + expf(-go));
    float cn = fmaf(sf, c_old, si * tanhf(gg));
    *c_new = cn;
    return so * tanhf(cn);
}

// ---------------------------------------------------------------------------
// Iteration-0 LSTM for BOTH node and edge: gates = permuted bias, c_old = 0.
// ---------------------------------------------------------------------------
__global__ void lstm_first_kernel(const float* __restrict__ bn,
                                  const float* __restrict__ be,
                                  float* __restrict__ cn,
                                  float* __restrict__ ce,
                                  float* __restrict__ qcat) {
    int idx = blockIdx.x * blockDim.x + threadIdx.x;
    const int NTOT = BGRAPH * DN;
    const int ETOT = BGRAPH * DE;
    if (idx >= NTOT + ETOT) return;
    if (idx < NTOT) {
        int b = idx / DN, d = idx % DN;
        float cv;
        float h = lstm_cell(bn[4*d], bn[4*d+1], bn[4*d+2], bn[4*d+3], 0.f, &cv);
        cn[idx] = cv;
        qcat[(size_t)b * 768 + d] = h;
    } else {
        int e = idx - NTOT;
        int b = e / DE, d = e % DE;
        float cv;
        float h = lstm_cell(be[4*d], be[4*d+1], be[4*d+2], be[4*d+3], 0.f, &cv);
        ce[e] = cv;
        qcat[(size_t)b * 768 + 512 + d] = h;
    }
}

// ---------------------------------------------------------------------------
// Fused tensor gate-GEMM + LSTM update for BOTH LSTMs in one launch.
// Reads q_star from qcat_in, writes new h into qcat_out (DIFFERENT buffer:
// no cross-CTA read/write race). Grid (24, 32): bx<16 node, else edge.
// ---------------------------------------------------------------------------
#define GS_LD 68
__global__ __launch_bounds__(128)
void gates_lstm_tc_kernel(const float* __restrict__ qcat_in,
                          const float* __restrict__ Wn, const float* __restrict__ bn,
                          float* __restrict__ cn,
                          const float* __restrict__ We, const float* __restrict__ be,
                          float* __restrict__ ce,
                          float* __restrict__ qcat_out) {
    __shared__ float sm[4 * SM_TILE];

    int tid = threadIdx.x;
    int bx = blockIdx.x;
    bool is_edge = bx >= 16;

    const float* A     = is_edge ? (qcat_in + 512) : qcat_in;
    const float* B     = is_edge ? We : Wn;
    const float* biasP = is_edge ? be : bn;
    float* c           = is_edge ? ce : cn;
    int K              = is_edge ? 256 : 512;
    int D              = is_edge ? 128 : 256;
    int h_off          = is_edge ? 512 : 0;
    int bcol           = (is_edge ? (bx - 16) : bx) * 64;
    int brow           = blockIdx.y * 64;

    float4 acc[2][4];
#pragma unroll
    for (int i = 0; i < 2; i++)
#pragma unroll
        for (int j = 0; j < 4; j++) acc[i][j] = make_float4(0.f, 0.f, 0.f, 0.f);

    tf32_mainloop<true>(A, 768, B, K, 0, brow, bcol, sm, acc, tid);

    // Store accum fragments to Gs [64][GS_LD]
    float* Gs = sm;
    int lane = tid & 31, warp = tid >> 5;
    int wm = (warp >> 1) * 32, wn = (warp & 1) * 32;
    int l4 = lane & 3, lg = lane >> 2;
#pragma unroll
    for (int mt = 0; mt < 2; mt++) {
        int r0 = wm + mt * 16 + lg;
#pragma unroll
        for (int nt = 0; nt < 4; nt++) {
            int c0 = wn + nt * 8 + l4 * 2;
            *(float2*)&Gs[r0 * GS_LD + c0]       = make_float2(acc[mt][nt].x, acc[mt][nt].y);
            *(float2*)&Gs[(r0 + 8) * GS_LD + c0] = make_float2(acc[mt][nt].z, acc[mt][nt].w);
        }
    }
    __syncthreads();

    // LSTM epilogue
    int r = tid >> 1;
    int uo = (tid & 1) * 8;
    int row = brow + r;
#pragma unroll
    for (int uu = 0; uu < 8; uu++) {
        int ul = uo + uu;
        float4 g = *(const float4*)&Gs[r * GS_LD + ul * 4];
        int cglob = bcol + ul * 4;
        int ug = cglob >> 2;
        float c_old = c[(size_t)row * D + ug];
        float cv;
        float h = lstm_cell(g.x + biasP[cglob], g.y + biasP[cglob + 1],
                            g.z + biasP[cglob + 2], g.w + biasP[cglob + 3],
                            c_old, &cv);
        c[(size_t)row * D + ug] = cv;
        qcat_out[(size_t)row * 768 + h_off + ug] = h;
    }
}

// ---------------------------------------------------------------------------
// Plain tensor GEMM (64x64 tiles): C = A @ B (+bias, optional relu).
// ---------------------------------------------------------------------------
template<bool RELU>
__global__ __launch_bounds__(128)
void tgemm_kernel(const float* __restrict__ A, int lda,
                  const float* __restrict__ B,
                  const float* __restrict__ bias,
                  float* __restrict__ C, int ldc,
                  int N, int K) {
    __shared__ float sm[4 * SM_TILE];

    int tid = threadIdx.x;
    int brow = blockIdx.y * 64;
    int bcol = blockIdx.x * 64;

    float4 acc[2][4];
#pragma unroll
    for (int i = 0; i < 2; i++)
#pragma unroll
        for (int j = 0; j < 4; j++) acc[i][j] = make_float4(0.f, 0.f, 0.f, 0.f);

    tf32_mainloop<false>(A, lda, B, K, N, brow, bcol, sm, acc, tid);

    int lane = tid & 31, warp = tid >> 5;
    int wm = (warp >> 1) * 32, wn = (warp & 1) * 32;
    int l4 = lane & 3, lg = lane >> 2;
#pragma unroll
    for (int mt = 0; mt < 2; mt++) {
        int r0 = brow + wm + mt * 16 + lg;
#pragma unroll
        for (int nt = 0; nt < 4; nt++) {
            int c0 = bcol + wn + nt * 8 + l4 * 2;
            float b0 = bias[c0], b1 = bias[c0 + 1];
            float2 v0 = make_float2(acc[mt][nt].x + b0, acc[mt][nt].y + b1);
            float2 v1 = make_float2(acc[mt][nt].z + b0, acc[mt][nt].w + b1);
            if (RELU) {
                v0.x = fmaxf(v0.x, 0.f); v0.y = fmaxf(v0.y, 0.f);
                v1.x = fmaxf(v1.x, 0.f); v1.y = fmaxf(v1.y, 0.f);
            }
            *(float2*)(C + (size_t)r0 * ldc + c0)       = v0;
            *(float2*)(C + (size_t)(r0 + 8) * ldc + c0) = v1;
        }
    }
}

// ---------------------------------------------------------------------------
// Unified segment-softmax attention + readout (node + edge in one launch).
// ---------------------------------------------------------------------------
__global__ __launch_bounds__(256)
void attn_kernel(const float* __restrict__ node_feat,
                 const float* __restrict__ edge_feat,
                 const int* __restrict__ starts_n,
                 const int* __restrict__ starts_e,
                 float* __restrict__ qcat_io) {
    __shared__ float qsh[256];
    __shared__ float sc[1024];
    __shared__ float red[32];

    int blk = blockIdx.x;
    bool is_edge = blk >= BGRAPH;
    int b = is_edge ? (blk - BGRAPH) : blk;
    const float* feat  = is_edge ? edge_feat : node_feat;
    const int* starts  = is_edge ? starts_e : starts_n;
    int D      = is_edge ? 128 : 256;
    int q_off  = is_edge ? 512 : 0;
    int r_off  = is_edge ? 640 : 256;
    int EPL    = D >> 5;

    int tid = threadIdx.x;
    int warp = tid >> 5, lane = tid & 31;

    if (tid < D) qsh[tid] = qcat_io[(size_t)b * 768 + q_off + tid];
    int s = starts[b], e = starts[b + 1];
    int cnt = e - s;
    if (cnt > 1024) cnt = 1024;
    __syncthreads();

    for (int j = warp; j < cnt; j += 8) {
        const float* frow = feat + (size_t)(s + j) * D;
        float sum = 0.f;
        for (int u = 0; u < EPL; u++)
            sum = fmaf(frow[lane + 32 * u], qsh[lane + 32 * u], sum);
#pragma unroll
        for (int o = 16; o > 0; o >>= 1) sum += __shfl_xor_sync(0xFFFFFFFFu, sum, o);
        if (lane == 0) sc[j] = sum;
    }
    __syncthreads();

    float m = -INFINITY;
    for (int j = tid; j < cnt; j += 256) m = fmaxf(m, sc[j]);
#pragma unroll
    for (int o = 16; o > 0; o >>= 1) m = fmaxf(m, __shfl_xor_sync(0xFFFFFFFFu, m, o));
    if (lane == 0) red[warp] = m;
    __syncthreads();
    if (tid < 32) {
        float v = (tid < 8) ? red[tid] : -INFINITY;
#pragma unroll
        for (int o = 16; o > 0; o >>= 1) v = fmaxf(v, __shfl_xor_sync(0xFFFFFFFFu, v, o));
        if (tid == 0) red[0] = v;
    }
    __syncthreads();
    m = red[0];
    __syncthreads();

    float lsum = 0.f;
    for (int j = tid; j < cnt; j += 256) {
        float ev = expf(sc[j] - m);
        sc[j] = ev;
        lsum += ev;
    }
#pragma unroll
    for (int o = 16; o > 0; o >>= 1) lsum += __shfl_xor_sync(0xFFFFFFFFu, lsum, o);
    if (lane == 0) red[warp] = lsum;
    __syncthreads();
    if (tid < 32) {
        float v = (tid < 8) ? red[tid] : 0.f;
#pragma unroll
        for (int o = 16; o > 0; o >>= 1) v += __shfl_xor_sync(0xFFFFFFFFu, v, o);
        if (tid == 0) red[0] = v;
    }
    __syncthreads();
    float den = red[0];
    float inv = (den > 0.f) ? 1.f / den : 0.f;
    for (int j = tid; j < cnt; j += 256) sc[j] *= inv;
    __syncthreads();

    if (tid < D) {
        float acc = 0.f;
        for (int j = 0; j < cnt; j++)
            acc = fmaf(feat[(size_t)(s + j) * D + tid], sc[j], acc);
        qcat_io[(size_t)b * 768 + r_off + tid] = acc;
    }
}

// ---------------------------------------------------------------------------
// Final layer: out[b] = dot(x4[b,:512], Wf3) + bf3. One warp per row.
// ---------------------------------------------------------------------------
__global__ void final_dot_kernel(const float* __restrict__ x,
                                 const float* __restrict__ w,
                                 const float* __restrict__ b3,
                                 float* __restrict__ out) {
    int row = blockIdx.x * (blockDim.x >> 5) + (threadIdx.x >> 5);
    int lane = threadIdx.x & 31;
    if (row >= BGRAPH) return;
    const float* xr = x + (size_t)row * 512;
    float s = 0.f;
#pragma unroll
    for (int k = lane; k < 512; k += 32) s = fmaf(xr[k], w[k], s);
#pragma unroll
    for (int o = 16; o > 0; o >>= 1) s += __shfl_xor_sync(0xFFFFFFFFu, s, o);
    if (lane == 0) out[row] = s + b3[0];
}

// ---------------------------------------------------------------------------
// Launch. Ping-pong qcat: gate GEMM reads qc[cur], writes h into qc[nxt];
// attention reads/writes qc[nxt]; cur flips.
// ---------------------------------------------------------------------------
extern "C" void kernel_launch(void* const* d_in, const int* in_sizes, int n_in,
                              void* d_out, int out_size) {
    const float* node_feat = (const float*)d_in[0];
    const float* edge_feat = (const float*)d_in[1];
    const int*   node_seg  = (const int*)  d_in[2];
    const int*   edge_seg  = (const int*)  d_in[3];
    const float* Wih_n = (const float*)d_in[4];
    const float* Whh_n = (const float*)d_in[5];
    const float* bih_n = (const float*)d_in[6];
    const float* bhh_n = (const float*)d_in[7];
    const float* Wih_e = (const float*)d_in[8];
    const float* Whh_e = (const float*)d_in[9];
    const float* bih_e = (const float*)d_in[10];
    const float* bhh_e = (const float*)d_in[11];
    const float* Wd1 = (const float*)d_in[12];
    const float* bd1 = (const float*)d_in[13];
    const float* Wd2 = (const float*)d_in[14];
    const float* bd2 = (const float*)d_in[15];
    const float* Wf1 = (const float*)d_in[16];
    const float* bf1 = (const float*)d_in[17];
    const float* Wf2 = (const float*)d_in[18];
    const float* bf2 = (const float*)d_in[19];
    const float* Wf3 = (const float*)d_in[20];
    const float* bf3 = (const float*)d_in[21];
    float* out = (float*)d_out;

    float* base;
    int *stn, *ste;
    cudaGetSymbolAddress((void**)&base, g_scratch);
    cudaGetSymbolAddress((void**)&stn, g_starts_n);
    cudaGetSymbolAddress((void**)&ste, g_starts_e);

    float* qc[2] = { base + OFF_QC0, base + OFF_QC1 };
    float* cn   = base + OFF_CN;
    float* ce   = base + OFF_CE;
    float* Wn   = base + OFF_WN;
    float* bn   = base + OFF_BN;
    float* We   = base + OFF_WE;
    float* be   = base + OFF_BE;
    float* x1   = base + OFF_X1;
    float* o2   = base + OFF_O2;
    float* x3   = base + OFF_X3;
    float* x4   = base + OFF_X4;

    seg_starts_kernel<<<dim3(9, 2), 256>>>(node_seg, edge_seg, stn, ste);
    prep_w_kernel<<<(1024 * 512 + 255) / 256, 256>>>(Wih_n, Whh_n, bih_n, bhh_n, Wn, bn,
                                                     1024, 512, 256);
    prep_w_kernel<<<(512 * 256 + 255) / 256, 256>>>(Wih_e, Whh_e, bih_e, bhh_e, We, be,
                                                    512, 256, 128);

    int cur = 0;   // buffer holding the up-to-date q_star state
    for (int t = 0; t < NITER; t++) {
        if (t == 0) {
            lstm_first_kernel<<<(2048 * 384 + 255) / 256, 256>>>(bn, be, cn, ce, qc[cur]);
        } else {
            int nxt = cur ^ 1;
            gates_lstm_tc_kernel<<<dim3(24, 32), 128>>>(qc[cur], Wn, bn, cn,
                                                        We, be, ce, qc[nxt]);
            cur = nxt;
        }
        attn_kernel<<<2 * BGRAPH, 256>>>(node_feat, edge_feat, stn, ste, qc[cur]);
    }

    // Decode + FFN (tensor path)
    tgemm_kernel<true ><<<dim3(8, 32), 128>>>(qc[cur], 768, Wd1, bd1, x1, 512, 512, 768);
    tgemm_kernel<false><<<dim3(32, 32), 128>>>(x1, 512, Wd2, bd2, o2, 2048, 2048, 512);
    tgemm_kernel<true ><<<dim3(8, 32), 128>>>(o2, 2048, Wf1, bf1, x3, 512, 512, 2048);
    tgemm_kernel<true ><<<dim3(8, 32), 128>>>(x3, 512, Wf2, bf2, x4, 512, 512, 512);
    final_dot_kernel<<<BGRAPH / 8, 256>>>(x4, Wf3, bf3, out);
}